// round 7
// baseline (speedup 1.0000x reference)
#include <cuda_runtime.h>
#include <cuda_bf16.h>
#include <cstdint>

// =======================================================================
// bf16 mma.sync fused MoE-PINN. 512 threads/CTA (16 warps, 4/SMSP),
// warp tile 16x32, cp.async 4-deep weight pipeline (16-k stages).
// =======================================================================

__device__ __nv_bfloat16 g_We1b[6 * 512 * 1024];
__device__ __nv_bfloat16 g_We2b[6 * 1024 * 512];
__device__ float g_routing[32768 * 6];

__device__ __forceinline__ float fast_tanh(float x) {
    float e = __expf(2.0f * x);
    return 1.0f - __fdividef(2.0f, e + 1.0f);
}
__device__ __forceinline__ uint32_t smem_u32(const void* p) {
    return (uint32_t)__cvta_generic_to_shared(p);
}
__device__ __forceinline__ void ldsm_x4(uint32_t (&r)[4], uint32_t a) {
    asm volatile("ldmatrix.sync.aligned.m8n8.x4.shared.b16 {%0,%1,%2,%3}, [%4];"
        : "=r"(r[0]), "=r"(r[1]), "=r"(r[2]), "=r"(r[3]) : "r"(a));
}
__device__ __forceinline__ void ldsm_x4_t(uint32_t (&r)[4], uint32_t a) {
    asm volatile("ldmatrix.sync.aligned.m8n8.x4.trans.shared.b16 {%0,%1,%2,%3}, [%4];"
        : "=r"(r[0]), "=r"(r[1]), "=r"(r[2]), "=r"(r[3]) : "r"(a));
}
__device__ __forceinline__ void mma_bf16(float (&d)[4], const uint32_t (&a)[4],
                                         uint32_t b0, uint32_t b1) {
    asm volatile(
        "mma.sync.aligned.m16n8k16.row.col.f32.bf16.bf16.f32 "
        "{%0,%1,%2,%3}, {%4,%5,%6,%7}, {%8,%9}, {%0,%1,%2,%3};"
        : "+f"(d[0]), "+f"(d[1]), "+f"(d[2]), "+f"(d[3])
        : "r"(a[0]), "r"(a[1]), "r"(a[2]), "r"(a[3]), "r"(b0), "r"(b1));
}
__device__ __forceinline__ void cp16(uint32_t dst, const void* src) {
    asm volatile("cp.async.cg.shared.global [%0], [%1], 16;" :: "r"(dst), "l"(src));
}
__device__ __forceinline__ void cp_commit() {
    asm volatile("cp.async.commit_group;");
}
__device__ __forceinline__ void cp_wait2() {
    asm volatile("cp.async.wait_group 2;");
}

// ---------------- prep: convert We1/We2 to bf16 ----------------
__global__ __launch_bounds__(256) void prep_kernel(
    const float* __restrict__ We1, const float* __restrict__ We2)
{
    const size_t N4 = (size_t)6 * 512 * 1024 / 4;
    size_t i = (size_t)blockIdx.x * 256 + threadIdx.x;
    if (i < N4) {
        float4 v = ((const float4*)We1)[i];
        ((__nv_bfloat162*)g_We1b)[i * 2]     = __floats2bfloat162_rn(v.x, v.y);
        ((__nv_bfloat162*)g_We1b)[i * 2 + 1] = __floats2bfloat162_rn(v.z, v.w);
        float4 w = ((const float4*)We2)[i];
        ((__nv_bfloat162*)g_We2b)[i * 2]     = __floats2bfloat162_rn(w.x, w.y);
        ((__nv_bfloat162*)g_We2b)[i * 2 + 1] = __floats2bfloat162_rn(w.z, w.w);
    }
}

// ---------------- routing kernel (fp32, unchanged) ----------------
__global__ __launch_bounds__(256, 1) void routing_kernel(
    const float* __restrict__ x,
    const float* __restrict__ Wr1, const float* __restrict__ br1,
    const float* __restrict__ Wr2, const float* __restrict__ br2)
{
    extern __shared__ char smraw[];
    float* xs = (float*)smraw;
    float* w1 = xs + 64 * 512;
    float* r1 = w1 + 512 * 32;
    float* w2 = r1 + 64 * 32;
    float* b1 = w2 + 192;
    float* b2 = b1 + 32;

    const int s = blockIdx.y;
    const int b0 = blockIdx.x * 64;
    const int tid = threadIdx.x;

    for (int i = tid; i < 64 * 512 / 4; i += 256) {
        int row = i >> 7, c4 = i & 127;
        ((float4*)xs)[i] = *(const float4*)(x + (size_t)(b0 + row) * 4096 + s * 512 + c4 * 4);
    }
    const float* w1g = Wr1 + (size_t)s * 512 * 32;
    for (int i = tid; i < 512 * 32 / 4; i += 256)
        ((float4*)w1)[i] = ((const float4*)w1g)[i];
    if (tid < 32)  b1[tid] = br1[s * 32 + tid];
    if (tid < 192) w2[tid] = Wr2[s * 192 + tid];
    if (tid < 6)   b2[tid] = br2[s * 6 + tid];
    __syncthreads();

    {
        int h = tid & 31, rg = tid >> 5;
        float acc[8];
#pragma unroll
        for (int r = 0; r < 8; ++r) acc[r] = 0.f;
        for (int k = 0; k < 512; ++k) {
            float w = w1[k * 32 + h];
#pragma unroll
            for (int r = 0; r < 8; ++r)
                acc[r] = fmaf(xs[(rg * 8 + r) * 512 + k], w, acc[r]);
        }
#pragma unroll
        for (int r = 0; r < 8; ++r)
            r1[(rg * 8 + r) * 32 + h] = fmaxf(acc[r] + b1[h], 0.f);
    }
    __syncthreads();

    if (tid < 64) {
        float lg[6];
#pragma unroll
        for (int e = 0; e < 6; ++e) lg[e] = b2[e];
        for (int h = 0; h < 32; ++h) {
            float rv = r1[tid * 32 + h];
#pragma unroll
            for (int e = 0; e < 6; ++e) lg[e] = fmaf(rv, w2[h * 6 + e], lg[e]);
        }
        float mx = lg[0];
#pragma unroll
        for (int e = 1; e < 6; ++e) mx = fmaxf(mx, lg[e]);
        float sum = 0.f;
#pragma unroll
        for (int e = 0; e < 6; ++e) { lg[e] = __expf(lg[e] - mx); sum += lg[e]; }
        float inv = 1.f / sum;
        int r = (b0 + tid) * 8 + s;
#pragma unroll
        for (int e = 0; e < 6; ++e) g_routing[r * 6 + e] = lg[e] * inv;
    }
}

// ---------------- tensor-core GEMM chunk, cp.async pipeline ----------------
#define LDA_X 520
#define LDA_H1 1032
#define WS_STRIDE 136
#define WS_BUF_E (16 * WS_STRIDE)      // elems per buffer
#define WS_BUF_B (WS_BUF_E * 2)        // bytes per buffer

// Warp grid 4(m) x 4(n): warp tile 16 rows x 32 cols of the 64x128 chunk.
template <int MODE>
__device__ __forceinline__ void mma_chunk(
    const __nv_bfloat16* __restrict__ Asm, int lda, int K,
    const __nv_bfloat16* __restrict__ Wg, int ldw,
    const __nv_bfloat16* __restrict__ ws, uint32_t ws_u32,
    const float* __restrict__ biasg,
    __nv_bfloat16* __restrict__ h1out, int nc,
    const float* __restrict__ we3s, float (*s)[3])
{
    const int tid = threadIdx.x;
    const int lane = tid & 31, warp = tid >> 5;
    const int wr = warp >> 2, wc = warp & 3;
    const int rowbase = wr * 16, colbase = wc * 32;
    const int li = lane & 15, lj = lane >> 4;

    float c[4][4];
#pragma unroll
    for (int nt = 0; nt < 4; ++nt)
#pragma unroll
        for (int v = 0; v < 4; ++v) c[nt][v] = 0.f;

    // cp.async: 16 rows x 128 cols per stage, 16B/thread, threads 0..255
    const int crow = tid >> 4;            // 0..31 (only <16 used)
    const int ccol = (tid & 15) * 8;
    const uint32_t dst0 = ws_u32 + (uint32_t)((crow & 15) * WS_STRIDE + ccol) * 2;
    const __nv_bfloat16* src0 = Wg + (size_t)(crow & 15) * ldw + ccol;
    const bool cpth = (tid < 256);
    const int nst = K >> 4;

#pragma unroll
    for (int q = 0; q < 3; ++q) {
        if (cpth) cp16(dst0 + (uint32_t)q * WS_BUF_B, src0 + (size_t)q * 16 * ldw);
        cp_commit();
    }

    const __nv_bfloat16* a0 = Asm + (size_t)(rowbase + li) * lda + lj * 8;
    const __nv_bfloat16* bp = ws + li * WS_STRIDE + colbase + lj * 8;

    for (int st = 0; st < nst; ++st) {
        cp_wait2();
        __syncthreads();
        if (cpth && st + 3 < nst)
            cp16(dst0 + (uint32_t)((st + 3) & 3) * WS_BUF_B,
                 src0 + (size_t)(st + 3) * 16 * ldw);
        cp_commit();

        uint32_t a[4], b[2][4];
        ldsm_x4(a, smem_u32(a0 + st * 16));
        const __nv_bfloat16* wb = bp + (st & 3) * WS_BUF_E;
        ldsm_x4_t(b[0], smem_u32(wb));
        ldsm_x4_t(b[1], smem_u32(wb + 16));

#pragma unroll
        for (int nt = 0; nt < 4; ++nt)
            mma_bf16(c[nt], a, b[nt >> 1][(nt & 1) * 2], b[nt >> 1][(nt & 1) * 2 + 1]);
    }

    // epilogue
#pragma unroll
    for (int nt = 0; nt < 4; ++nt) {
        const int colc = colbase + nt * 8 + 2 * (lane & 3);
        float2 bb = *(const float2*)(biasg + colc);
        float t0 = fast_tanh(c[nt][0] + bb.x);
        float t1 = fast_tanh(c[nt][1] + bb.y);
        float t2 = fast_tanh(c[nt][2] + bb.x);
        float t3 = fast_tanh(c[nt][3] + bb.y);
        const int ra = rowbase + (lane >> 2);
        if (MODE == 0) {
            __nv_bfloat162 p0 = __floats2bfloat162_rn(t0, t1);
            __nv_bfloat162 p1 = __floats2bfloat162_rn(t2, t3);
            *(__nv_bfloat162*)&h1out[(size_t)ra * LDA_H1 + nc + colc] = p0;
            *(__nv_bfloat162*)&h1out[(size_t)(ra + 8) * LDA_H1 + nc + colc] = p1;
        } else {
            const int cg = nc + colc;
            const float* w3a = we3s + (size_t)cg * 3;
            const float* w3b = w3a + 3;
#pragma unroll
            for (int o = 0; o < 3; ++o) {
                float wa = w3a[o], wb2 = w3b[o];
                s[0][o] += t0 * wa + t1 * wb2;
                s[1][o] += t2 * wa + t3 * wb2;
            }
        }
    }
}

// ---------------- main fused kernel: 512 CTAs x 512 threads ----------------
// smem: xs 66560 | h1 132096 | ws 17408 | we3s 6144 | rout 1536 | oacc 1024
//       total 224768
__global__ __launch_bounds__(512, 1) void moe_kernel(
    const float* __restrict__ x,
    const float* __restrict__ be1, const float* __restrict__ be2,
    const float* __restrict__ We3, const float* __restrict__ be3,
    const float* __restrict__ Wa1, const float* __restrict__ ba1,
    const float* __restrict__ Wa2, const float* __restrict__ ba2,
    float* __restrict__ out)
{
    extern __shared__ char smraw[];
    __nv_bfloat16* xs   = (__nv_bfloat16*)(smraw);
    __nv_bfloat16* h1s  = (__nv_bfloat16*)(smraw + 66560);
    __nv_bfloat16* ws   = (__nv_bfloat16*)(smraw + 198656);
    float*         we3s = (float*)(smraw + 216064);
    float*         rout = (float*)(smraw + 222208);
    float*         oacc = (float*)(smraw + 223744);

    const int tid = threadIdx.x;
    const int lane = tid & 31, warp = tid >> 5;
    const int wr = warp >> 2, wc = warp & 3;
    const int r0 = blockIdx.x * 64;
    const uint32_t ws_u32 = smem_u32(ws);

    for (int i = tid; i < 64 * 512 / 4; i += 512) {
        int row = i >> 7, c4 = i & 127;
        float4 v = *(const float4*)(x + (size_t)(r0 + row) * 512 + c4 * 4);
        __nv_bfloat162* d = (__nv_bfloat162*)&xs[(size_t)row * LDA_X + c4 * 4];
        d[0] = __floats2bfloat162_rn(v.x, v.y);
        d[1] = __floats2bfloat162_rn(v.z, v.w);
    }
    if (tid < 384) rout[tid] = g_routing[(size_t)r0 * 6 + tid];
    if (tid < 256) oacc[tid] = 0.f;
    __syncthreads();

    for (int e = 0; e < 6; ++e) {
        // barrier: previous expert's we3s readers + oacc atomics done before rewrite
        __syncthreads();
        for (int i = tid; i < 1536; i += 512)
            we3s[i] = We3[(size_t)e * 1536 + i];
        // (ordered before first use by the first in-loop __syncthreads of chunk 0)

        // L1: h1 = tanh(x @ We1 + be1)
        const __nv_bfloat16* W1 = g_We1b + (size_t)e * 512 * 1024;
        const float* b1 = be1 + e * 1024;
        for (int nc = 0; nc < 1024; nc += 128)
            mma_chunk<0>(xs, LDA_X, 512, W1 + nc, 1024, ws, ws_u32, b1 + nc,
                         h1s, nc, nullptr, nullptr);

        // L2+L3 fused
        float s[2][3];
#pragma unroll
        for (int rt = 0; rt < 2; ++rt)
#pragma unroll
            for (int o = 0; o < 3; ++o) s[rt][o] = 0.f;

        const __nv_bfloat16* W2 = g_We2b + (size_t)e * 1024 * 512;
        const float* b2 = be2 + e * 512;
        for (int nc = 0; nc < 512; nc += 128)
            mma_chunk<1>(h1s, LDA_H1, 1024, W2 + nc, 512, ws, ws_u32, b2 + nc,
                         nullptr, nc, we3s, s);

        // reduce the 4 lanes sharing each row, then routing-weighted accumulate
#pragma unroll
        for (int rt = 0; rt < 2; ++rt)
#pragma unroll
            for (int o = 0; o < 3; ++o) {
                s[rt][o] += __shfl_xor_sync(0xffffffffu, s[rt][o], 1);
                s[rt][o] += __shfl_xor_sync(0xffffffffu, s[rt][o], 2);
            }
        if ((lane & 3) == 0) {
            float bz[3];
#pragma unroll
            for (int o = 0; o < 3; ++o)
                bz[o] = (wc == 0) ? be3[e * 3 + o] : 0.f;
#pragma unroll
            for (int rt = 0; rt < 2; ++rt) {
                int row = wr * 16 + (lane >> 2) + 8 * rt;
                float rw = rout[row * 6 + e];
#pragma unroll
                for (int o = 0; o < 3; ++o)
                    atomicAdd(&oacc[row * 4 + o], rw * (s[rt][o] + bz[o]));
            }
        }
    }
    __syncthreads();

    // block mean + aggregator (8 batch items per CTA)
    if (tid < 8) {
        float f0 = 0.f, f1 = 0.f, f2 = 0.f;
#pragma unroll
        for (int i = 0; i < 8; ++i) {
            f0 += oacc[(tid * 8 + i) * 4 + 0];
            f1 += oacc[(tid * 8 + i) * 4 + 1];
            f2 += oacc[(tid * 8 + i) * 4 + 2];
        }
        f0 *= 0.125f; f1 *= 0.125f; f2 *= 0.125f;
        float a1[16];
#pragma unroll
        for (int j = 0; j < 16; ++j) {
            float v = ba1[j] + f0 * Wa1[j] + f1 * Wa1[16 + j] + f2 * Wa1[32 + j];
            a1[j] = fmaxf(v, 0.f);
        }
        int b = blockIdx.x * 8 + tid;
#pragma unroll
        for (int o = 0; o < 3; ++o) {
            float v = ba2[o];
#pragma unroll
            for (int j = 0; j < 16; ++j) v = fmaf(a1[j], Wa2[j * 3 + o], v);
            out[b * 3 + o] = v;
        }
    }
}

// ---------------- launch ----------------
extern "C" void kernel_launch(void* const* d_in, const int* in_sizes, int n_in,
                              void* d_out, int out_size) {
    const float* x   = (const float*)d_in[0];
    const float* Wr1 = (const float*)d_in[1];
    const float* br1 = (const float*)d_in[2];
    const float* Wr2 = (const float*)d_in[3];
    const float* br2 = (const float*)d_in[4];
    const float* We1 = (const float*)d_in[5];
    const float* be1 = (const float*)d_in[6];
    const float* We2 = (const float*)d_in[7];
    const float* be2 = (const float*)d_in[8];
    const float* We3 = (const float*)d_in[9];
    const float* be3 = (const float*)d_in[10];
    const float* Wa1 = (const float*)d_in[11];
    const float* ba1 = (const float*)d_in[12];
    const float* Wa2 = (const float*)d_in[13];
    const float* ba2 = (const float*)d_in[14];
    float* out = (float*)d_out;

    const int SMEM_R = (64 * 512 + 512 * 32 + 64 * 32 + 192 + 32 + 8) * 4;
    const int SMEM_M = 224768;

    cudaFuncSetAttribute(routing_kernel, cudaFuncAttributeMaxDynamicSharedMemorySize, SMEM_R);
    cudaFuncSetAttribute(moe_kernel, cudaFuncAttributeMaxDynamicSharedMemorySize, SMEM_M);

    prep_kernel<<<3072, 256>>>(We1, We2);
    routing_kernel<<<dim3(64, 8), 256, SMEM_R>>>(x, Wr1, br1, Wr2, br2);
    moe_kernel<<<512, 512, SMEM_M>>>(x, be1, be2, We3, be3,
                                     Wa1, ba1, Wa2, ba2, out);
}

// round 8
// speedup vs baseline: 1.0009x; 1.0009x over previous
#include <cuda_runtime.h>
#include <cuda_bf16.h>
#include <cstdint>

// =======================================================================
// bf16 mma.sync fused MoE-PINN. 512 threads/CTA (16 warps, 4/SMSP),
// warp tile 16x32, cp.async 4-deep weight pipeline (16-k stages).
// =======================================================================

__device__ __nv_bfloat16 g_We1b[6 * 512 * 1024];
__device__ __nv_bfloat16 g_We2b[6 * 1024 * 512];
__device__ float g_routing[32768 * 6];

__device__ __forceinline__ float fast_tanh(float x) {
    float e = __expf(2.0f * x);
    return 1.0f - __fdividef(2.0f, e + 1.0f);
}
__device__ __forceinline__ uint32_t smem_u32(const void* p) {
    return (uint32_t)__cvta_generic_to_shared(p);
}
__device__ __forceinline__ void ldsm_x4(uint32_t (&r)[4], uint32_t a) {
    asm volatile("ldmatrix.sync.aligned.m8n8.x4.shared.b16 {%0,%1,%2,%3}, [%4];"
        : "=r"(r[0]), "=r"(r[1]), "=r"(r[2]), "=r"(r[3]) : "r"(a));
}
__device__ __forceinline__ void ldsm_x4_t(uint32_t (&r)[4], uint32_t a) {
    asm volatile("ldmatrix.sync.aligned.m8n8.x4.trans.shared.b16 {%0,%1,%2,%3}, [%4];"
        : "=r"(r[0]), "=r"(r[1]), "=r"(r[2]), "=r"(r[3]) : "r"(a));
}
__device__ __forceinline__ void mma_bf16(float (&d)[4], const uint32_t (&a)[4],
                                         uint32_t b0, uint32_t b1) {
    asm volatile(
        "mma.sync.aligned.m16n8k16.row.col.f32.bf16.bf16.f32 "
        "{%0,%1,%2,%3}, {%4,%5,%6,%7}, {%8,%9}, {%0,%1,%2,%3};"
        : "+f"(d[0]), "+f"(d[1]), "+f"(d[2]), "+f"(d[3])
        : "r"(a[0]), "r"(a[1]), "r"(a[2]), "r"(a[3]), "r"(b0), "r"(b1));
}
__device__ __forceinline__ void cp16(uint32_t dst, const void* src) {
    asm volatile("cp.async.cg.shared.global [%0], [%1], 16;" :: "r"(dst), "l"(src));
}
__device__ __forceinline__ void cp_commit() {
    asm volatile("cp.async.commit_group;");
}
__device__ __forceinline__ void cp_wait2() {
    asm volatile("cp.async.wait_group 2;");
}

// ---------------- prep: convert We1/We2 to bf16 ----------------
__global__ __launch_bounds__(256) void prep_kernel(
    const float* __restrict__ We1, const float* __restrict__ We2)
{
    const size_t N4 = (size_t)6 * 512 * 1024 / 4;
    size_t i = (size_t)blockIdx.x * 256 + threadIdx.x;
    if (i < N4) {
        float4 v = ((const float4*)We1)[i];
        ((__nv_bfloat162*)g_We1b)[i * 2]     = __floats2bfloat162_rn(v.x, v.y);
        ((__nv_bfloat162*)g_We1b)[i * 2 + 1] = __floats2bfloat162_rn(v.z, v.w);
        float4 w = ((const float4*)We2)[i];
        ((__nv_bfloat162*)g_We2b)[i * 2]     = __floats2bfloat162_rn(w.x, w.y);
        ((__nv_bfloat162*)g_We2b)[i * 2 + 1] = __floats2bfloat162_rn(w.z, w.w);
    }
}

// ---------------- routing kernel (fp32, unchanged) ----------------
__global__ __launch_bounds__(256, 1) void routing_kernel(
    const float* __restrict__ x,
    const float* __restrict__ Wr1, const float* __restrict__ br1,
    const float* __restrict__ Wr2, const float* __restrict__ br2)
{
    extern __shared__ char smraw[];
    float* xs = (float*)smraw;
    float* w1 = xs + 64 * 512;
    float* r1 = w1 + 512 * 32;
    float* w2 = r1 + 64 * 32;
    float* b1 = w2 + 192;
    float* b2 = b1 + 32;

    const int s = blockIdx.y;
    const int b0 = blockIdx.x * 64;
    const int tid = threadIdx.x;

    for (int i = tid; i < 64 * 512 / 4; i += 256) {
        int row = i >> 7, c4 = i & 127;
        ((float4*)xs)[i] = *(const float4*)(x + (size_t)(b0 + row) * 4096 + s * 512 + c4 * 4);
    }
    const float* w1g = Wr1 + (size_t)s * 512 * 32;
    for (int i = tid; i < 512 * 32 / 4; i += 256)
        ((float4*)w1)[i] = ((const float4*)w1g)[i];
    if (tid < 32)  b1[tid] = br1[s * 32 + tid];
    if (tid < 192) w2[tid] = Wr2[s * 192 + tid];
    if (tid < 6)   b2[tid] = br2[s * 6 + tid];
    __syncthreads();

    {
        int h = tid & 31, rg = tid >> 5;
        float acc[8];
#pragma unroll
        for (int r = 0; r < 8; ++r) acc[r] = 0.f;
        for (int k = 0; k < 512; ++k) {
            float w = w1[k * 32 + h];
#pragma unroll
            for (int r = 0; r < 8; ++r)
                acc[r] = fmaf(xs[(rg * 8 + r) * 512 + k], w, acc[r]);
        }
#pragma unroll
        for (int r = 0; r < 8; ++r)
            r1[(rg * 8 + r) * 32 + h] = fmaxf(acc[r] + b1[h], 0.f);
    }
    __syncthreads();

    if (tid < 64) {
        float lg[6];
#pragma unroll
        for (int e = 0; e < 6; ++e) lg[e] = b2[e];
        for (int h = 0; h < 32; ++h) {
            float rv = r1[tid * 32 + h];
#pragma unroll
            for (int e = 0; e < 6; ++e) lg[e] = fmaf(rv, w2[h * 6 + e], lg[e]);
        }
        float mx = lg[0];
#pragma unroll
        for (int e = 1; e < 6; ++e) mx = fmaxf(mx, lg[e]);
        float sum = 0.f;
#pragma unroll
        for (int e = 0; e < 6; ++e) { lg[e] = __expf(lg[e] - mx); sum += lg[e]; }
        float inv = 1.f / sum;
        int r = (b0 + tid) * 8 + s;
#pragma unroll
        for (int e = 0; e < 6; ++e) g_routing[r * 6 + e] = lg[e] * inv;
    }
}

// ---------------- tensor-core GEMM chunk, cp.async pipeline ----------------
#define LDA_X 520
#define LDA_H1 1032
#define WS_STRIDE 136
#define WS_BUF_E (16 * WS_STRIDE)      // elems per buffer
#define WS_BUF_B (WS_BUF_E * 2)        // bytes per buffer

// Warp grid 4(m) x 4(n): warp tile 16 rows x 32 cols of the 64x128 chunk.
template <int MODE>
__device__ __forceinline__ void mma_chunk(
    const __nv_bfloat16* __restrict__ Asm, int lda, int K,
    const __nv_bfloat16* __restrict__ Wg, int ldw,
    const __nv_bfloat16* __restrict__ ws, uint32_t ws_u32,
    const float* __restrict__ biasg,
    __nv_bfloat16* __restrict__ h1out, int nc,
    const float* __restrict__ we3s, float (*s)[3])
{
    const int tid = threadIdx.x;
    const int lane = tid & 31, warp = tid >> 5;
    const int wr = warp >> 2, wc = warp & 3;
    const int rowbase = wr * 16, colbase = wc * 32;
    const int li = lane & 15, lj = lane >> 4;

    float c[4][4];
#pragma unroll
    for (int nt = 0; nt < 4; ++nt)
#pragma unroll
        for (int v = 0; v < 4; ++v) c[nt][v] = 0.f;

    // cp.async: 16 rows x 128 cols per stage, 16B/thread, threads 0..255
    const int crow = tid >> 4;            // 0..31 (only <16 used)
    const int ccol = (tid & 15) * 8;
    const uint32_t dst0 = ws_u32 + (uint32_t)((crow & 15) * WS_STRIDE + ccol) * 2;
    const __nv_bfloat16* src0 = Wg + (size_t)(crow & 15) * ldw + ccol;
    const bool cpth = (tid < 256);
    const int nst = K >> 4;

#pragma unroll
    for (int q = 0; q < 3; ++q) {
        if (cpth) cp16(dst0 + (uint32_t)q * WS_BUF_B, src0 + (size_t)q * 16 * ldw);
        cp_commit();
    }

    const __nv_bfloat16* a0 = Asm + (size_t)(rowbase + li) * lda + lj * 8;
    const __nv_bfloat16* bp = ws + li * WS_STRIDE + colbase + lj * 8;

    for (int st = 0; st < nst; ++st) {
        cp_wait2();
        __syncthreads();
        if (cpth && st + 3 < nst)
            cp16(dst0 + (uint32_t)((st + 3) & 3) * WS_BUF_B,
                 src0 + (size_t)(st + 3) * 16 * ldw);
        cp_commit();

        uint32_t a[4], b[2][4];
        ldsm_x4(a, smem_u32(a0 + st * 16));
        const __nv_bfloat16* wb = bp + (st & 3) * WS_BUF_E;
        ldsm_x4_t(b[0], smem_u32(wb));
        ldsm_x4_t(b[1], smem_u32(wb + 16));

#pragma unroll
        for (int nt = 0; nt < 4; ++nt)
            mma_bf16(c[nt], a, b[nt >> 1][(nt & 1) * 2], b[nt >> 1][(nt & 1) * 2 + 1]);
    }

    // epilogue
#pragma unroll
    for (int nt = 0; nt < 4; ++nt) {
        const int colc = colbase + nt * 8 + 2 * (lane & 3);
        float2 bb = *(const float2*)(biasg + colc);
        float t0 = fast_tanh(c[nt][0] + bb.x);
        float t1 = fast_tanh(c[nt][1] + bb.y);
        float t2 = fast_tanh(c[nt][2] + bb.x);
        float t3 = fast_tanh(c[nt][3] + bb.y);
        const int ra = rowbase + (lane >> 2);
        if (MODE == 0) {
            __nv_bfloat162 p0 = __floats2bfloat162_rn(t0, t1);
            __nv_bfloat162 p1 = __floats2bfloat162_rn(t2, t3);
            *(__nv_bfloat162*)&h1out[(size_t)ra * LDA_H1 + nc + colc] = p0;
            *(__nv_bfloat162*)&h1out[(size_t)(ra + 8) * LDA_H1 + nc + colc] = p1;
        } else {
            const int cg = nc + colc;
            const float* w3a = we3s + (size_t)cg * 3;
            const float* w3b = w3a + 3;
#pragma unroll
            for (int o = 0; o < 3; ++o) {
                float wa = w3a[o], wb2 = w3b[o];
                s[0][o] += t0 * wa + t1 * wb2;
                s[1][o] += t2 * wa + t3 * wb2;
            }
        }
    }
}

// ---------------- main fused kernel: 512 CTAs x 512 threads ----------------
// smem: xs 66560 | h1 132096 | ws 17408 | we3s 6144 | rout 1536 | oacc 1024
//       total 224768
__global__ __launch_bounds__(512, 1) void moe_kernel(
    const float* __restrict__ x,
    const float* __restrict__ be1, const float* __restrict__ be2,
    const float* __restrict__ We3, const float* __restrict__ be3,
    const float* __restrict__ Wa1, const float* __restrict__ ba1,
    const float* __restrict__ Wa2, const float* __restrict__ ba2,
    float* __restrict__ out)
{
    extern __shared__ char smraw[];
    __nv_bfloat16* xs   = (__nv_bfloat16*)(smraw);
    __nv_bfloat16* h1s  = (__nv_bfloat16*)(smraw + 66560);
    __nv_bfloat16* ws   = (__nv_bfloat16*)(smraw + 198656);
    float*         we3s = (float*)(smraw + 216064);
    float*         rout = (float*)(smraw + 222208);
    float*         oacc = (float*)(smraw + 223744);

    const int tid = threadIdx.x;
    const int lane = tid & 31, warp = tid >> 5;
    const int wr = warp >> 2, wc = warp & 3;
    const int r0 = blockIdx.x * 64;
    const uint32_t ws_u32 = smem_u32(ws);

    for (int i = tid; i < 64 * 512 / 4; i += 512) {
        int row = i >> 7, c4 = i & 127;
        float4 v = *(const float4*)(x + (size_t)(r0 + row) * 512 + c4 * 4);
        __nv_bfloat162* d = (__nv_bfloat162*)&xs[(size_t)row * LDA_X + c4 * 4];
        d[0] = __floats2bfloat162_rn(v.x, v.y);
        d[1] = __floats2bfloat162_rn(v.z, v.w);
    }
    if (tid < 384) rout[tid] = g_routing[(size_t)r0 * 6 + tid];
    if (tid < 256) oacc[tid] = 0.f;
    __syncthreads();

    for (int e = 0; e < 6; ++e) {
        // barrier: previous expert's we3s readers + oacc atomics done before rewrite
        __syncthreads();
        for (int i = tid; i < 1536; i += 512)
            we3s[i] = We3[(size_t)e * 1536 + i];
        // (ordered before first use by the first in-loop __syncthreads of chunk 0)

        // L1: h1 = tanh(x @ We1 + be1)
        const __nv_bfloat16* W1 = g_We1b + (size_t)e * 512 * 1024;
        const float* b1 = be1 + e * 1024;
        for (int nc = 0; nc < 1024; nc += 128)
            mma_chunk<0>(xs, LDA_X, 512, W1 + nc, 1024, ws, ws_u32, b1 + nc,
                         h1s, nc, nullptr, nullptr);

        // L2+L3 fused
        float s[2][3];
#pragma unroll
        for (int rt = 0; rt < 2; ++rt)
#pragma unroll
            for (int o = 0; o < 3; ++o) s[rt][o] = 0.f;

        const __nv_bfloat16* W2 = g_We2b + (size_t)e * 1024 * 512;
        const float* b2 = be2 + e * 512;
        for (int nc = 0; nc < 512; nc += 128)
            mma_chunk<1>(h1s, LDA_H1, 1024, W2 + nc, 512, ws, ws_u32, b2 + nc,
                         nullptr, nc, we3s, s);

        // reduce the 4 lanes sharing each row, then routing-weighted accumulate
#pragma unroll
        for (int rt = 0; rt < 2; ++rt)
#pragma unroll
            for (int o = 0; o < 3; ++o) {
                s[rt][o] += __shfl_xor_sync(0xffffffffu, s[rt][o], 1);
                s[rt][o] += __shfl_xor_sync(0xffffffffu, s[rt][o], 2);
            }
        if ((lane & 3) == 0) {
            float bz[3];
#pragma unroll
            for (int o = 0; o < 3; ++o)
                bz[o] = (wc == 0) ? be3[e * 3 + o] : 0.f;
#pragma unroll
            for (int rt = 0; rt < 2; ++rt) {
                int row = wr * 16 + (lane >> 2) + 8 * rt;
                float rw = rout[row * 6 + e];
#pragma unroll
                for (int o = 0; o < 3; ++o)
                    atomicAdd(&oacc[row * 4 + o], rw * (s[rt][o] + bz[o]));
            }
        }
    }
    __syncthreads();

    // block mean + aggregator (8 batch items per CTA)
    if (tid < 8) {
        float f0 = 0.f, f1 = 0.f, f2 = 0.f;
#pragma unroll
        for (int i = 0; i < 8; ++i) {
            f0 += oacc[(tid * 8 + i) * 4 + 0];
            f1 += oacc[(tid * 8 + i) * 4 + 1];
            f2 += oacc[(tid * 8 + i) * 4 + 2];
        }
        f0 *= 0.125f; f1 *= 0.125f; f2 *= 0.125f;
        float a1[16];
#pragma unroll
        for (int j = 0; j < 16; ++j) {
            float v = ba1[j] + f0 * Wa1[j] + f1 * Wa1[16 + j] + f2 * Wa1[32 + j];
            a1[j] = fmaxf(v, 0.f);
        }
        int b = blockIdx.x * 8 + tid;
#pragma unroll
        for (int o = 0; o < 3; ++o) {
            float v = ba2[o];
#pragma unroll
            for (int j = 0; j < 16; ++j) v = fmaf(a1[j], Wa2[j * 3 + o], v);
            out[b * 3 + o] = v;
        }
    }
}

// ---------------- launch ----------------
extern "C" void kernel_launch(void* const* d_in, const int* in_sizes, int n_in,
                              void* d_out, int out_size) {
    const float* x   = (const float*)d_in[0];
    const float* Wr1 = (const float*)d_in[1];
    const float* br1 = (const float*)d_in[2];
    const float* Wr2 = (const float*)d_in[3];
    const float* br2 = (const float*)d_in[4];
    const float* We1 = (const float*)d_in[5];
    const float* be1 = (const float*)d_in[6];
    const float* We2 = (const float*)d_in[7];
    const float* be2 = (const float*)d_in[8];
    const float* We3 = (const float*)d_in[9];
    const float* be3 = (const float*)d_in[10];
    const float* Wa1 = (const float*)d_in[11];
    const float* ba1 = (const float*)d_in[12];
    const float* Wa2 = (const float*)d_in[13];
    const float* ba2 = (const float*)d_in[14];
    float* out = (float*)d_out;

    const int SMEM_R = (64 * 512 + 512 * 32 + 64 * 32 + 192 + 32 + 8) * 4;
    const int SMEM_M = 224768;

    cudaFuncSetAttribute(routing_kernel, cudaFuncAttributeMaxDynamicSharedMemorySize, SMEM_R);
    cudaFuncSetAttribute(moe_kernel, cudaFuncAttributeMaxDynamicSharedMemorySize, SMEM_M);

    prep_kernel<<<3072, 256>>>(We1, We2);
    routing_kernel<<<dim3(64, 8), 256, SMEM_R>>>(x, Wr1, br1, Wr2, br2);
    moe_kernel<<<512, 512, SMEM_M>>>(x, be1, be2, We3, be3,
                                     Wa1, ba1, Wa2, ba2, out);
}